// round 15
// baseline (speedup 1.0000x reference)
#include <cuda_runtime.h>
#include <cuda_fp16.h>
#include <math.h>
#include <stdint.h>

#define D     1024
#define HD    4096
#define NE    8
#define TOPK  2
#define MAXT  8192
#define MAXROWS (MAXT * TOPK)
#define LN_EPS 1e-5f

// GEMM tiling
#define TM 128
#define TN 128
#define KC 64                        // 64 fp16 = 128B = swizzle atom row
#define TB 16384                     // one 128x64 fp16 tile
#define BUFB (2 * TB)                // A, B per stage (32 KB)
#define NSTAGE 3
#define SMEM_BYTES (NSTAGE * BUFB)   // 98304 -> 2 CTAs/SM
#define NTH 128                      // 4 warps, 64x64 warp tiles

// ---------------- scratch ----------------------------------------------------
__device__ __half g_xn [(size_t)MAXT * D];
__device__ __half g_h1 [(size_t)MAXROWS * HD];
__device__ __half g_w1 [(size_t)NE * HD * D];   // [E][H][D] transposed fp16
__device__ __half g_w2 [(size_t)NE * D * HD];   // [E][D][H] transposed fp16
__device__ float g_b1f[(size_t)NE * HD];
__device__ float g_y [(size_t)MAXROWS * D];
__device__ float g_wts[MAXROWS];
__device__ int   g_sel[MAXROWS];
__device__ int   g_rowmap[MAXROWS];
__device__ int   g_counts[NE];
__device__ int   g_offsets[NE + 1];
__device__ int   g_cursor[NE];

// ---------------- helpers ----------------------------------------------------
__device__ __forceinline__ uint32_t smem_u32(const void* p) {
    uint32_t a;
    asm("{ .reg .u64 t; cvta.to.shared.u64 t, %1; cvt.u32.u64 %0, t; }"
        : "=r"(a) : "l"(p));
    return a;
}
// swizzle: row stride 128B, XOR (row&7)*16 into column bits
#define SWZC(row, col) ((uint32_t)((row) * 128 + ((col) ^ (((row) & 7) * 16))))

#define CPASYNC16(dst, src) \
    asm volatile("cp.async.cg.shared.global [%0], [%1], 16;" \
                 :: "r"(dst), "l"(src))
#define CP_COMMIT() asm volatile("cp.async.commit_group;")
#define CP_WAIT1()  asm volatile("cp.async.wait_group 1;")
#define CP_WAIT0()  asm volatile("cp.async.wait_group 0;")

#define LDM4(r0, r1, r2, r3, addr) \
    asm volatile("ldmatrix.sync.aligned.m8n8.x4.shared.b16 {%0,%1,%2,%3}, [%4];" \
        : "=r"(r0), "=r"(r1), "=r"(r2), "=r"(r3) : "r"(addr))

#define MMA16816(c, a, b) \
    asm volatile("mma.sync.aligned.m16n8k16.row.col.f32.f16.f16.f32 " \
        "{%0,%1,%2,%3}, {%4,%5,%6,%7}, {%8,%9}, {%0,%1,%2,%3};" \
        : "+f"((c)[0]), "+f"((c)[1]), "+f"((c)[2]), "+f"((c)[3]) \
        : "r"((a)[0]), "r"((a)[1]), "r"((a)[2]), "r"((a)[3]), \
          "r"((b)[0]), "r"((b)[1]))

__device__ __forceinline__ uint32_t pack_h2(float a, float b) {
    __half2 h = __floats2half2_rn(a, b);
    return *reinterpret_cast<uint32_t*>(&h);
}

// ---------------- weight transpose + fp16 convert (+ optional scale fold) ----
__global__ __launch_bounds__(1024) void convw_kernel(
    const float* __restrict__ W, const float* __restrict__ scale,
    __half* __restrict__ oh, int KD, int NH)
{
    __shared__ float tile[32][33];
    const int e = blockIdx.z;
    const int dr = blockIdx.x * 32 + threadIdx.y;
    const int hr = blockIdx.y * 32 + threadIdx.x;
    tile[threadIdx.y][threadIdx.x] = W[((size_t)e * KD + dr) * NH + hr];
    __syncthreads();
    const int hw = blockIdx.y * 32 + threadIdx.y;
    const int dw = blockIdx.x * 32 + threadIdx.x;
    float v = tile[threadIdx.x][threadIdx.y];
    if (scale) v *= scale[(size_t)e * KD + dw];
    oh[((size_t)e * NH + hw) * KD + dw] = __float2half_rn(v);
}

// b1'[e][h] = b1[e][h] + sum_d ln_bias[e][d] * W1[e][d][h]
__global__ __launch_bounds__(256) void foldb1_kernel(
    const float* __restrict__ w1, const float* __restrict__ b1,
    const float* __restrict__ lnb)
{
    const int e = blockIdx.y;
    const int h = blockIdx.x * 256 + threadIdx.x;
    float acc = 0.f;
    const float* wp = w1 + (size_t)e * D * HD + h;
    const float* bp = lnb + (size_t)e * D;
    for (int d = 0; d < D; d++) acc = fmaf(bp[d], wp[(size_t)d * HD], acc);
    g_b1f[(size_t)e * HD + h] = b1[(size_t)e * HD + h] + acc;
}

// ---------------- routing ----------------------------------------------------
__global__ void init_kernel() {
    if (threadIdx.x < NE) g_counts[threadIdx.x] = 0;
}

__global__ __launch_bounds__(256) void gate_ln_kernel(
    const float* __restrict__ x, const float* __restrict__ gw)
{
    const int t   = blockIdx.x;
    const int tid = threadIdx.x;
    __shared__ float sh_ws[8], sh_wq[8], sh_wl[8][8];
    __shared__ float sh_mu, sh_rstd;

    const float4 xv = reinterpret_cast<const float4*>(x + (size_t)t * D)[tid];
    float s = xv.x + xv.y + xv.z + xv.w;
    float q = xv.x * xv.x + xv.y * xv.y + xv.z * xv.z + xv.w * xv.w;

    float acc[8];
#pragma unroll
    for (int e = 0; e < 8; e++) acc[e] = 0.f;
    const float xs[4] = {xv.x, xv.y, xv.z, xv.w};
#pragma unroll
    for (int j = 0; j < 4; j++) {
        const int d = tid * 4 + j;
        const float4 g0 = *reinterpret_cast<const float4*>(gw + (size_t)d * 8);
        const float4 g1 = *reinterpret_cast<const float4*>(gw + (size_t)d * 8 + 4);
        const float xj = xs[j];
        acc[0] = fmaf(xj, g0.x, acc[0]); acc[1] = fmaf(xj, g0.y, acc[1]);
        acc[2] = fmaf(xj, g0.z, acc[2]); acc[3] = fmaf(xj, g0.w, acc[3]);
        acc[4] = fmaf(xj, g1.x, acc[4]); acc[5] = fmaf(xj, g1.y, acc[5]);
        acc[6] = fmaf(xj, g1.z, acc[6]); acc[7] = fmaf(xj, g1.w, acc[7]);
    }
#pragma unroll
    for (int o = 16; o > 0; o >>= 1) {
        s += __shfl_xor_sync(0xffffffffu, s, o);
        q += __shfl_xor_sync(0xffffffffu, q, o);
#pragma unroll
        for (int e = 0; e < 8; e++)
            acc[e] += __shfl_xor_sync(0xffffffffu, acc[e], o);
    }
    const int wid = tid >> 5, lane = tid & 31;
    if (lane == 0) {
        sh_ws[wid] = s; sh_wq[wid] = q;
#pragma unroll
        for (int e = 0; e < 8; e++) sh_wl[wid][e] = acc[e];
    }
    __syncthreads();

    if (tid == 0) {
        float S = 0.f, Q = 0.f, L[8];
#pragma unroll
        for (int e = 0; e < 8; e++) L[e] = 0.f;
        for (int w = 0; w < 8; w++) {
            S += sh_ws[w]; Q += sh_wq[w];
#pragma unroll
            for (int e = 0; e < 8; e++) L[e] += sh_wl[w][e];
        }
        const float mu = S * (1.f / (float)D);
        float var = Q * (1.f / (float)D) - mu * mu;
        if (var < 0.f) var = 0.f;
        sh_mu = mu; sh_rstd = rsqrtf(var + LN_EPS);

        float mx = L[0];
#pragma unroll
        for (int e = 1; e < 8; e++) mx = fmaxf(mx, L[e]);
        float p[8], se = 0.f;
#pragma unroll
        for (int e = 0; e < 8; e++) { p[e] = expf(L[e] - mx); se += p[e]; }
        const float inv = 1.f / se;
#pragma unroll
        for (int e = 0; e < 8; e++) p[e] *= inv;

        int i0 = 0; float p0 = p[0];
#pragma unroll
        for (int e = 1; e < 8; e++) if (p[e] > p0) { p0 = p[e]; i0 = e; }
        int i1 = -1; float p1 = -1e30f;
#pragma unroll
        for (int e = 0; e < 8; e++)
            if (e != i0 && p[e] > p1) { p1 = p[e]; i1 = e; }

        const float ew = expf(p1 - p0);
        g_sel[2 * t] = i0;  g_sel[2 * t + 1] = i1;
        g_wts[2 * t] = 1.f / (1.f + ew);
        g_wts[2 * t + 1] = ew / (1.f + ew);
        atomicAdd(&g_counts[i0], 1);
        atomicAdd(&g_counts[i1], 1);
    }
    __syncthreads();

    const float mu = sh_mu, rstd = sh_rstd;
    uint32_t* o = reinterpret_cast<uint32_t*>(g_xn + (size_t)t * D);
    o[tid * 2]     = pack_h2((xv.x - mu) * rstd, (xv.y - mu) * rstd);
    o[tid * 2 + 1] = pack_h2((xv.z - mu) * rstd, (xv.w - mu) * rstd);
}

__global__ void offsets_kernel() {
    if (threadIdx.x == 0) {
        int o = 0;
        for (int e = 0; e < NE; e++) {
            g_offsets[e] = o; g_cursor[e] = o; o += g_counts[e];
        }
        g_offsets[NE] = o;
    }
}

__global__ void scatter_kernel(int total) {
    const int i = blockIdx.x * blockDim.x + threadIdx.x;
    if (i < total) {
        const int e = g_sel[i];
        const int pos = atomicAdd(&g_cursor[e], 1);
        g_rowmap[pos] = i;
    }
}

// ---------------- cp.async pipelined mma.sync grouped GEMM -------------------
// 4 warps, 64x64 warp tiles (2x2 grid): smem tiles read only 2x each.
template<bool G1>
__global__ __launch_bounds__(NTH, 2) void gemm_cp(
    const float* __restrict__ bias)
{
    constexpr int KTOT = G1 ? D : HD;
    constexpr int NTOT = G1 ? HD : D;
    constexpr int NC   = KTOT / KC;

    const int e    = blockIdx.z;
    const int seg0 = g_offsets[e];
    const int nseg = g_offsets[e + 1] - seg0;
    const int m0   = blockIdx.y * TM;
    if (m0 >= nseg) return;
    const int n0   = blockIdx.x * TN;

    extern __shared__ __align__(1024) char smem[];
    const uint32_t sb = smem_u32(smem);
    const int tid = threadIdx.x;

    // ---- copy mapping: one row per thread (row = tid), 8x16B per tile ----
    const int crow = tid;                 // 0..127
    const bool cval = (m0 + crow) < nseg;
    int arow;
    if (G1) arow = cval ? (g_rowmap[seg0 + m0 + crow] >> 1) : 0;
    else    arow = cval ? (seg0 + m0 + crow) : 0;
    const __half* srcA =
        (G1 ? g_xn + (size_t)arow * D : g_h1 + (size_t)arow * HD);
    const __half* srcB =
        (G1 ? g_w1 : g_w2) + ((size_t)e * NTOT + n0 + crow) * KTOT;

    uint32_t dstsw[8];
#pragma unroll
    for (int j = 0; j < 8; j++) dstsw[j] = SWZC(crow, j * 16);

    auto issue = [&](int stage, int c) {
        const uint32_t base = sb + stage * BUFB;
        const int kb = c * KC;
#pragma unroll
        for (int j = 0; j < 8; j++)
            CPASYNC16(base + dstsw[j], srcA + kb + j * 8);
#pragma unroll
        for (int j = 0; j < 8; j++)
            CPASYNC16(base + TB + dstsw[j], srcB + kb + j * 8);
        CP_COMMIT();
    };

    // ---- consumer: 4 warps, 2x2 grid of 64x64 tiles ----
    const int wid    = tid >> 5;
    const int lane   = tid & 31;
    const int warp_m = wid & 1;
    const int warp_n = wid >> 1;

    float acc[4][8][4];
#pragma unroll
    for (int i = 0; i < 4; i++)
#pragma unroll
        for (int j = 0; j < 8; j++)
#pragma unroll
            for (int k = 0; k < 4; k++) acc[i][j][k] = 0.f;

    const uint32_t sel   = (uint32_t)((lane & 7) << 4);
    const uint32_t rAoff = (uint32_t)((warp_m * 64 + ((lane >> 3) & 1) * 8 + (lane & 7)) * 128);
    const uint32_t cA16  = (uint32_t)((lane >> 4) * 16);
    const uint32_t rBoff = (uint32_t)((warp_n * 64 + (lane >> 4) * 8 + (lane & 7)) * 128);
    const uint32_t cB16  = (uint32_t)(((lane >> 3) & 1) * 16);

    auto compute = [&](int stage) {
        const uint32_t aB = sb + stage * BUFB;
        const uint32_t bB = aB + TB;
#pragma unroll
        for (int ks = 0; ks < 4; ks++) {
            const uint32_t colA = ((uint32_t)(ks * 32) + cA16) ^ sel;
            const uint32_t colB = ((uint32_t)(ks * 32) + cB16) ^ sel;
            uint32_t ah[4][4];
#pragma unroll
            for (int i = 0; i < 4; i++)
                LDM4(ah[i][0], ah[i][1], ah[i][2], ah[i][3],
                     aB + rAoff + (uint32_t)(i * 16 * 128) + colA);
#pragma unroll
            for (int half = 0; half < 2; half++) {
                uint32_t bh[4][2];
#pragma unroll
                for (int j2 = 0; j2 < 2; j2++) {
                    uint32_t t0, t1, t2, t3;
                    LDM4(t0, t1, t2, t3,
                         bB + rBoff + (uint32_t)((half * 2 + j2) * 16 * 128) + colB);
                    bh[2*j2][0]=t0; bh[2*j2][1]=t1; bh[2*j2+1][0]=t2; bh[2*j2+1][1]=t3;
                }
#pragma unroll
                for (int i = 0; i < 4; i++)
#pragma unroll
                    for (int j = 0; j < 4; j++)
                        MMA16816(acc[i][half * 4 + j], ah[i], bh[j]);
            }
        }
    };

    // ---- pipeline: 3 stages, 2 in flight ----
    issue(0, 0);
    issue(1, 1);
    int stage = 0;
    for (int c = 0; c < NC; c++) {
        if (c + 1 < NC) { CP_WAIT1(); } else { CP_WAIT0(); }
        __syncthreads();
        if (c + 2 < NC) {
            int s = stage + 2; if (s >= NSTAGE) s -= NSTAGE;
            issue(s, c + 2);
        }
        compute(stage);
        __syncthreads();
        if (++stage == NSTAGE) stage = 0;
    }

    // ---- epilogue ----
    {
        const int r4 = lane >> 2;
        const int c2 = 2 * (lane & 3);
        const int nb = n0 + warp_n * 64;
        const float* bp = G1 ? (g_b1f + (size_t)e * NTOT) : (bias + (size_t)e * NTOT);
        float2 bb[8];
#pragma unroll
        for (int j = 0; j < 8; j++)
            bb[j] = *reinterpret_cast<const float2*>(bp + nb + j * 8 + c2);
#pragma unroll
        for (int i = 0; i < 4; i++) {
#pragma unroll
            for (int h = 0; h < 2; h++) {
                const int mloc = warp_m * 64 + i * 16 + h * 8 + r4;
                if (m0 + mloc >= nseg) continue;
                if (G1) {
                    const size_t rb = (size_t)(seg0 + m0 + mloc) * HD + nb;
#pragma unroll
                    for (int j = 0; j < 8; j++) {
                        float y0 = acc[i][j][2*h]   + bb[j].x;
                        float y1 = acc[i][j][2*h+1] + bb[j].y;
                        y0 = 0.5f * y0 * (1.f + erff(y0 * 0.70710678118654752f));
                        y1 = 0.5f * y1 * (1.f + erff(y1 * 0.70710678118654752f));
                        reinterpret_cast<uint32_t*>(g_h1)[(rb + j * 8 + c2) >> 1] =
                            pack_h2(y0, y1);
                    }
                } else {
                    const int slot = g_rowmap[seg0 + m0 + mloc];
                    const float wt = g_wts[slot];
                    float* op = g_y + (size_t)slot * D + nb;
#pragma unroll
                    for (int j = 0; j < 8; j++) {
                        const float y0 = (acc[i][j][2*h]   + bb[j].x) * wt;
                        const float y1 = (acc[i][j][2*h+1] + bb[j].y) * wt;
                        *reinterpret_cast<float2*>(op + j * 8 + c2) = make_float2(y0, y1);
                    }
                }
            }
        }
    }
}

// ---------------- combine ----------------------------------------------------
__global__ void combine_kernel(float* __restrict__ out, int T) {
    const int nd4 = D / 4;
    const int i = blockIdx.x * blockDim.x + threadIdx.x;
    if (i >= T * nd4) return;
    const int t = i / nd4, d4 = i % nd4;
    const float4* y4 = reinterpret_cast<const float4*>(g_y);
    const float4 a = y4[(size_t)(2 * t) * nd4 + d4];
    const float4 b = y4[(size_t)(2 * t + 1) * nd4 + d4];
    reinterpret_cast<float4*>(out)[i] =
        make_float4(a.x + b.x, a.y + b.y, a.z + b.z, a.w + b.w);
}

// ---------------- launch -----------------------------------------------------
extern "C" void kernel_launch(void* const* d_in, const int* in_sizes, int n_in,
                              void* d_out, int out_size)
{
    const float* x   = (const float*)d_in[0];
    const float* gw  = (const float*)d_in[1];
    const float* lns = (const float*)d_in[2];
    const float* lnb = (const float*)d_in[3];
    const float* w1  = (const float*)d_in[4];
    const float* b1  = (const float*)d_in[5];
    const float* w2  = (const float*)d_in[6];
    const float* b2  = (const float*)d_in[7];
    float* out = (float*)d_out;

    const int T = in_sizes[0] / D;
    const int totalRows = T * TOPK;

    cudaFuncSetAttribute(gemm_cp<true>,
                         cudaFuncAttributeMaxDynamicSharedMemorySize, SMEM_BYTES);
    cudaFuncSetAttribute(gemm_cp<false>,
                         cudaFuncAttributeMaxDynamicSharedMemorySize, SMEM_BYTES);

    __half *w1p, *w2p;
    cudaGetSymbolAddress((void**)&w1p, g_w1);
    cudaGetSymbolAddress((void**)&w2p, g_w2);

    dim3 blk32(32, 32);
    convw_kernel<<<dim3(D / 32, HD / 32, NE), blk32>>>(w1, lns, w1p, D, HD);
    convw_kernel<<<dim3(HD / 32, D / 32, NE), blk32>>>(w2, nullptr, w2p, HD, D);
    foldb1_kernel<<<dim3(HD / 256, NE), 256>>>(w1, b1, lnb);

    init_kernel<<<1, 32>>>();
    gate_ln_kernel<<<T, 256>>>(x, gw);
    offsets_kernel<<<1, 32>>>();
    scatter_kernel<<<(totalRows + 255) / 256, 256>>>(totalRows);

    dim3 g1(HD / TN, (totalRows + TM - 1) / TM, NE);
    gemm_cp<true><<<g1, NTH, SMEM_BYTES>>>(nullptr);

    dim3 g2(D / TN, (totalRows + TM - 1) / TM, NE);
    gemm_cp<false><<<g2, NTH, SMEM_BYTES>>>(b2);

    combine_kernel<<<(T * (D / 4) + 255) / 256, 256>>>(out, T);
}

// round 16
// speedup vs baseline: 1.3151x; 1.3151x over previous
#include <cuda_runtime.h>
#include <cuda_fp16.h>
#include <math.h>
#include <stdint.h>

#define D     1024
#define HD    4096
#define NE    8
#define TOPK  2
#define MAXT  8192
#define MAXROWS (MAXT * TOPK)
#define LN_EPS 1e-5f

// GEMM tiling
#define TM 128
#define TN 128
#define KC 128                       // 128 k-elems per chunk = 2 subtiles of 64
#define TB 16384                     // one 128x64 fp16 tile
#define BUFB (4 * TB)                // A0,A1,B0,B1 per stage (64 KB)
#define NSTAGE 3
#define SMEM_BYTES (NSTAGE * BUFB)   // 196608
#define NTH 512

// ---------------- scratch ----------------------------------------------------
__device__ __half g_xn [(size_t)MAXT * D];
__device__ __half g_h1 [(size_t)MAXROWS * HD];
__device__ __half g_w1 [(size_t)NE * HD * D];   // [E][H][D] transposed fp16
__device__ __half g_w2 [(size_t)NE * D * HD];   // [E][D][H] transposed fp16
__device__ float g_b1f[(size_t)NE * HD];
__device__ float g_y [(size_t)MAXROWS * D];
__device__ float g_wts[MAXROWS];
__device__ int   g_sel[MAXROWS];
__device__ int   g_rowmap[MAXROWS];
__device__ int   g_counts[NE];
__device__ int   g_offsets[NE + 1];
__device__ int   g_cursor[NE];

// ---------------- helpers ----------------------------------------------------
__device__ __forceinline__ uint32_t smem_u32(const void* p) {
    uint32_t a;
    asm("{ .reg .u64 t; cvta.to.shared.u64 t, %1; cvt.u32.u64 %0, t; }"
        : "=r"(a) : "l"(p));
    return a;
}
// swizzle: row stride 128B, XOR (row&7)*16 into column bits
#define SWZC(row, col) ((uint32_t)((row) * 128 + ((col) ^ (((row) & 7) * 16))))

#define CPASYNC16(dst, src) \
    asm volatile("cp.async.cg.shared.global [%0], [%1], 16;" \
                 :: "r"(dst), "l"(src))
#define CP_COMMIT() asm volatile("cp.async.commit_group;")
#define CP_WAIT1()  asm volatile("cp.async.wait_group 1;")
#define CP_WAIT0()  asm volatile("cp.async.wait_group 0;")

#define LDM4(r0, r1, r2, r3, addr) \
    asm volatile("ldmatrix.sync.aligned.m8n8.x4.shared.b16 {%0,%1,%2,%3}, [%4];" \
        : "=r"(r0), "=r"(r1), "=r"(r2), "=r"(r3) : "r"(addr))

#define MMA16816(c, a, b) \
    asm volatile("mma.sync.aligned.m16n8k16.row.col.f32.f16.f16.f32 " \
        "{%0,%1,%2,%3}, {%4,%5,%6,%7}, {%8,%9}, {%0,%1,%2,%3};" \
        : "+f"((c)[0]), "+f"((c)[1]), "+f"((c)[2]), "+f"((c)[3]) \
        : "r"((a)[0]), "r"((a)[1]), "r"((a)[2]), "r"((a)[3]), \
          "r"((b)[0]), "r"((b)[1]))

__device__ __forceinline__ uint32_t pack_h2(float a, float b) {
    __half2 h = __floats2half2_rn(a, b);
    return *reinterpret_cast<uint32_t*>(&h);
}

// ---------------- weight transpose + fp16 convert (+ optional scale fold) ----
__global__ __launch_bounds__(1024) void convw_kernel(
    const float* __restrict__ W, const float* __restrict__ scale,
    __half* __restrict__ oh, int KD, int NH)
{
    __shared__ float tile[32][33];
    const int e = blockIdx.z;
    const int dr = blockIdx.x * 32 + threadIdx.y;
    const int hr = blockIdx.y * 32 + threadIdx.x;
    tile[threadIdx.y][threadIdx.x] = W[((size_t)e * KD + dr) * NH + hr];
    __syncthreads();
    const int hw = blockIdx.y * 32 + threadIdx.y;
    const int dw = blockIdx.x * 32 + threadIdx.x;
    float v = tile[threadIdx.x][threadIdx.y];
    if (scale) v *= scale[(size_t)e * KD + dw];
    oh[((size_t)e * NH + hw) * KD + dw] = __float2half_rn(v);
}

// b1'[e][h] = b1[e][h] + sum_d ln_bias[e][d] * W1[e][d][h]
__global__ __launch_bounds__(256) void foldb1_kernel(
    const float* __restrict__ w1, const float* __restrict__ b1,
    const float* __restrict__ lnb)
{
    const int e = blockIdx.y;
    const int h = blockIdx.x * 256 + threadIdx.x;
    float acc = 0.f;
    const float* wp = w1 + (size_t)e * D * HD + h;
    const float* bp = lnb + (size_t)e * D;
    for (int d = 0; d < D; d++) acc = fmaf(bp[d], wp[(size_t)d * HD], acc);
    g_b1f[(size_t)e * HD + h] = b1[(size_t)e * HD + h] + acc;
}

// ---------------- routing ----------------------------------------------------
__global__ void init_kernel() {
    if (threadIdx.x < NE) g_counts[threadIdx.x] = 0;
}

__global__ __launch_bounds__(256) void gate_ln_kernel(
    const float* __restrict__ x, const float* __restrict__ gw)
{
    const int t   = blockIdx.x;
    const int tid = threadIdx.x;
    __shared__ float sh_ws[8], sh_wq[8], sh_wl[8][8];
    __shared__ float sh_mu, sh_rstd;

    const float4 xv = reinterpret_cast<const float4*>(x + (size_t)t * D)[tid];
    float s = xv.x + xv.y + xv.z + xv.w;
    float q = xv.x * xv.x + xv.y * xv.y + xv.z * xv.z + xv.w * xv.w;

    float acc[8];
#pragma unroll
    for (int e = 0; e < 8; e++) acc[e] = 0.f;
    const float xs[4] = {xv.x, xv.y, xv.z, xv.w};
#pragma unroll
    for (int j = 0; j < 4; j++) {
        const int d = tid * 4 + j;
        const float4 g0 = *reinterpret_cast<const float4*>(gw + (size_t)d * 8);
        const float4 g1 = *reinterpret_cast<const float4*>(gw + (size_t)d * 8 + 4);
        const float xj = xs[j];
        acc[0] = fmaf(xj, g0.x, acc[0]); acc[1] = fmaf(xj, g0.y, acc[1]);
        acc[2] = fmaf(xj, g0.z, acc[2]); acc[3] = fmaf(xj, g0.w, acc[3]);
        acc[4] = fmaf(xj, g1.x, acc[4]); acc[5] = fmaf(xj, g1.y, acc[5]);
        acc[6] = fmaf(xj, g1.z, acc[6]); acc[7] = fmaf(xj, g1.w, acc[7]);
    }
#pragma unroll
    for (int o = 16; o > 0; o >>= 1) {
        s += __shfl_xor_sync(0xffffffffu, s, o);
        q += __shfl_xor_sync(0xffffffffu, q, o);
#pragma unroll
        for (int e = 0; e < 8; e++)
            acc[e] += __shfl_xor_sync(0xffffffffu, acc[e], o);
    }
    const int wid = tid >> 5, lane = tid & 31;
    if (lane == 0) {
        sh_ws[wid] = s; sh_wq[wid] = q;
#pragma unroll
        for (int e = 0; e < 8; e++) sh_wl[wid][e] = acc[e];
    }
    __syncthreads();

    if (tid == 0) {
        float S = 0.f, Q = 0.f, L[8];
#pragma unroll
        for (int e = 0; e < 8; e++) L[e] = 0.f;
        for (int w = 0; w < 8; w++) {
            S += sh_ws[w]; Q += sh_wq[w];
#pragma unroll
            for (int e = 0; e < 8; e++) L[e] += sh_wl[w][e];
        }
        const float mu = S * (1.f / (float)D);
        float var = Q * (1.f / (float)D) - mu * mu;
        if (var < 0.f) var = 0.f;
        sh_mu = mu; sh_rstd = rsqrtf(var + LN_EPS);

        float mx = L[0];
#pragma unroll
        for (int e = 1; e < 8; e++) mx = fmaxf(mx, L[e]);
        float p[8], se = 0.f;
#pragma unroll
        for (int e = 0; e < 8; e++) { p[e] = expf(L[e] - mx); se += p[e]; }
        const float inv = 1.f / se;
#pragma unroll
        for (int e = 0; e < 8; e++) p[e] *= inv;

        int i0 = 0; float p0 = p[0];
#pragma unroll
        for (int e = 1; e < 8; e++) if (p[e] > p0) { p0 = p[e]; i0 = e; }
        int i1 = -1; float p1 = -1e30f;
#pragma unroll
        for (int e = 0; e < 8; e++)
            if (e != i0 && p[e] > p1) { p1 = p[e]; i1 = e; }

        const float ew = expf(p1 - p0);
        g_sel[2 * t] = i0;  g_sel[2 * t + 1] = i1;
        g_wts[2 * t] = 1.f / (1.f + ew);
        g_wts[2 * t + 1] = ew / (1.f + ew);
        atomicAdd(&g_counts[i0], 1);
        atomicAdd(&g_counts[i1], 1);
    }
    __syncthreads();

    const float mu = sh_mu, rstd = sh_rstd;
    uint32_t* o = reinterpret_cast<uint32_t*>(g_xn + (size_t)t * D);
    o[tid * 2]     = pack_h2((xv.x - mu) * rstd, (xv.y - mu) * rstd);
    o[tid * 2 + 1] = pack_h2((xv.z - mu) * rstd, (xv.w - mu) * rstd);
}

__global__ void offsets_kernel() {
    if (threadIdx.x == 0) {
        int o = 0;
        for (int e = 0; e < NE; e++) {
            g_offsets[e] = o; g_cursor[e] = o; o += g_counts[e];
        }
        g_offsets[NE] = o;
    }
}

__global__ void scatter_kernel(int total) {
    const int i = blockIdx.x * blockDim.x + threadIdx.x;
    if (i < total) {
        const int e = g_sel[i];
        const int pos = atomicAdd(&g_cursor[e], 1);
        g_rowmap[pos] = i;
    }
}

// ---------------- cp.async pipelined mma.sync grouped GEMM -------------------
// 16 warps, 32x32 warp tiles; KC=128 chunks; single barrier per chunk.
template<bool G1>
__global__ __launch_bounds__(NTH, 1) void gemm_cp(
    const float* __restrict__ bias)
{
    constexpr int KTOT = G1 ? D : HD;
    constexpr int NTOT = G1 ? HD : D;
    constexpr int NC   = KTOT / KC;

    const int e    = blockIdx.z;
    const int seg0 = g_offsets[e];
    const int nseg = g_offsets[e + 1] - seg0;
    const int m0   = blockIdx.y * TM;
    if (m0 >= nseg) return;
    const int n0   = blockIdx.x * TN;

    extern __shared__ __align__(1024) char smem[];
    const uint32_t sb = smem_u32(smem);
    const int tid = threadIdx.x;

    // copy mapping: row = tid>>2, 32B-quarter = tid&3; per chunk each thread
    // copies 2x16B per subtile-plane (A0,A1,B0,B1) = 8 cp.async
    const int crow = tid >> 2;
    const int cq   = tid & 3;
    const bool cval = (m0 + crow) < nseg;
    int arow;
    if (G1) arow = cval ? (g_rowmap[seg0 + m0 + crow] >> 1) : 0;
    else    arow = cval ? (seg0 + m0 + crow) : 0;
    const __half* srcA =
        (G1 ? g_xn + (size_t)arow * D : g_h1 + (size_t)arow * HD);
    const __half* srcB =
        (G1 ? g_w1 : g_w2) + ((size_t)e * NTOT + n0 + crow) * KTOT;

    const uint32_t dst0 = SWZC(crow, cq * 32);
    const uint32_t dst1 = SWZC(crow, cq * 32 + 16);

    auto issue = [&](int stage, int c) {
        const uint32_t base = sb + stage * BUFB;
        const int kb = c * KC;
#pragma unroll
        for (int t = 0; t < 2; t++) {
            const int ko = kb + t * 64 + cq * 16;
            CPASYNC16(base + t * TB + dst0, srcA + ko);
            CPASYNC16(base + t * TB + dst1, srcA + ko + 8);
            CPASYNC16(base + (2 + t) * TB + dst0, srcB + ko);
            CPASYNC16(base + (2 + t) * TB + dst1, srcB + ko + 8);
        }
        CP_COMMIT();
    };

    // consumer: 16 warps, 32x32 warp tiles
    const int wid    = tid >> 5;
    const int lane   = tid & 31;
    const int warp_m = wid & 3;
    const int warp_n = wid >> 2;

    float acc[2][4][4];
#pragma unroll
    for (int i = 0; i < 2; i++)
#pragma unroll
        for (int j = 0; j < 4; j++)
#pragma unroll
            for (int k = 0; k < 4; k++) acc[i][j][k] = 0.f;

    const uint32_t sel    = (uint32_t)((lane & 7) << 4);
    const uint32_t rowAb  = (uint32_t)((warp_m * 32 + ((lane >> 3) & 1) * 8 + (lane & 7)) * 128);
    const uint32_t colA16 = (uint32_t)((lane >> 4) * 16);
    const uint32_t rowBb  = (uint32_t)((warp_n * 32 + (lane >> 4) * 8 + (lane & 7)) * 128);
    const uint32_t colB16 = (uint32_t)(((lane >> 3) & 1) * 16);

    auto compute = [&](int stage) {
        const uint32_t base = sb + stage * BUFB;
#pragma unroll
        for (int ks = 0; ks < 8; ks++) {
            const uint32_t aB = base + (ks >> 2) * TB;
            const uint32_t bB = base + (2 + (ks >> 2)) * TB;
            const uint32_t kcol = (uint32_t)((ks & 3) * 32);
            const uint32_t colA = (kcol + colA16) ^ sel;
            const uint32_t colB = (kcol + colB16) ^ sel;
            uint32_t ah[2][4], bh[4][2];
#pragma unroll
            for (int i = 0; i < 2; i++)
                LDM4(ah[i][0], ah[i][1], ah[i][2], ah[i][3],
                     aB + rowAb + (uint32_t)(i * 16 * 128) + colA);
#pragma unroll
            for (int j2 = 0; j2 < 2; j2++) {
                uint32_t t0, t1, t2, t3;
                LDM4(t0, t1, t2, t3, bB + rowBb + (uint32_t)(j2 * 16 * 128) + colB);
                bh[2*j2][0]=t0; bh[2*j2][1]=t1; bh[2*j2+1][0]=t2; bh[2*j2+1][1]=t3;
            }
#pragma unroll
            for (int i = 0; i < 2; i++)
#pragma unroll
                for (int j = 0; j < 4; j++) MMA16816(acc[i][j], ah[i], bh[j]);
        }
    };

    // pipeline: 3 stages, 2 in flight, ONE barrier per chunk
    issue(0, 0);
    issue(1, 1);
    int stage = 0;
    for (int c = 0; c < NC; c++) {
        if (c + 1 < NC) { CP_WAIT1(); } else { CP_WAIT0(); }
        __syncthreads();           // chunk c ready for all; compute(c-1) done for all
        if (c + 2 < NC) {
            int s = stage + 2; if (s >= NSTAGE) s -= NSTAGE;
            issue(s, c + 2);
        }
        compute(stage);
        if (++stage == NSTAGE) stage = 0;
    }
    __syncthreads();

    // epilogue
    {
        const int r4 = lane >> 2;
        const int c2 = 2 * (lane & 3);
        const int nb = n0 + warp_n * 32;
        const float* bp = G1 ? (g_b1f + (size_t)e * NTOT) : (bias + (size_t)e * NTOT);
        float2 bb[4];
#pragma unroll
        for (int j = 0; j < 4; j++)
            bb[j] = *reinterpret_cast<const float2*>(bp + nb + j * 8 + c2);
#pragma unroll
        for (int i = 0; i < 2; i++) {
#pragma unroll
            for (int h = 0; h < 2; h++) {
                const int mloc = warp_m * 32 + i * 16 + h * 8 + r4;
                if (m0 + mloc >= nseg) continue;
                if (G1) {
                    const size_t rb = (size_t)(seg0 + m0 + mloc) * HD + nb;
#pragma unroll
                    for (int j = 0; j < 4; j++) {
                        float y0 = acc[i][j][2*h]   + bb[j].x;
                        float y1 = acc[i][j][2*h+1] + bb[j].y;
                        y0 = 0.5f * y0 * (1.f + erff(y0 * 0.70710678118654752f));
                        y1 = 0.5f * y1 * (1.f + erff(y1 * 0.70710678118654752f));
                        reinterpret_cast<uint32_t*>(g_h1)[(rb + j * 8 + c2) >> 1] =
                            pack_h2(y0, y1);
                    }
                } else {
                    const int slot = g_rowmap[seg0 + m0 + mloc];
                    const float wt = g_wts[slot];
                    float* op = g_y + (size_t)slot * D + nb;
#pragma unroll
                    for (int j = 0; j < 4; j++) {
                        const float y0 = (acc[i][j][2*h]   + bb[j].x) * wt;
                        const float y1 = (acc[i][j][2*h+1] + bb[j].y) * wt;
                        *reinterpret_cast<float2*>(op + j * 8 + c2) = make_float2(y0, y1);
                    }
                }
            }
        }
    }
}

// ---------------- combine ----------------------------------------------------
__global__ void combine_kernel(float* __restrict__ out, int T) {
    const int nd4 = D / 4;
    const int i = blockIdx.x * blockDim.x + threadIdx.x;
    if (i >= T * nd4) return;
    const int t = i / nd4, d4 = i % nd4;
    const float4* y4 = reinterpret_cast<const float4*>(g_y);
    const float4 a = y4[(size_t)(2 * t) * nd4 + d4];
    const float4 b = y4[(size_t)(2 * t + 1) * nd4 + d4];
    reinterpret_cast<float4*>(out)[i] =
        make_float4(a.x + b.x, a.y + b.y, a.z + b.z, a.w + b.w);
}

// ---------------- launch -----------------------------------------------------
extern "C" void kernel_launch(void* const* d_in, const int* in_sizes, int n_in,
                              void* d_out, int out_size)
{
    const float* x   = (const float*)d_in[0];
    const float* gw  = (const float*)d_in[1];
    const float* lns = (const float*)d_in[2];
    const float* lnb = (const float*)d_in[3];
    const float* w1  = (const float*)d_in[4];
    const float* b1  = (const float*)d_in[5];
    const float* w2  = (const float*)d_in[6];
    const float* b2  = (const float*)d_in[7];
    float* out = (float*)d_out;

    const int T = in_sizes[0] / D;
    const int totalRows = T * TOPK;

    cudaFuncSetAttribute(gemm_cp<true>,
                         cudaFuncAttributeMaxDynamicSharedMemorySize, SMEM_BYTES);
    cudaFuncSetAttribute(gemm_cp<false>,
                         cudaFuncAttributeMaxDynamicSharedMemorySize, SMEM_BYTES);

    __half *w1p, *w2p;
    cudaGetSymbolAddress((void**)&w1p, g_w1);
    cudaGetSymbolAddress((void**)&w2p, g_w2);

    dim3 blk32(32, 32);
    convw_kernel<<<dim3(D / 32, HD / 32, NE), blk32>>>(w1, lns, w1p, D, HD);
    convw_kernel<<<dim3(HD / 32, D / 32, NE), blk32>>>(w2, nullptr, w2p, HD, D);
    foldb1_kernel<<<dim3(HD / 256, NE), 256>>>(w1, b1, lnb);

    init_kernel<<<1, 32>>>();
    gate_ln_kernel<<<T, 256>>>(x, gw);
    offsets_kernel<<<1, 32>>>();
    scatter_kernel<<<(totalRows + 255) / 256, 256>>>(totalRows);

    dim3 g1(HD / TN, (totalRows + TM - 1) / TM, NE);
    gemm_cp<true><<<g1, NTH, SMEM_BYTES>>>(nullptr);

    dim3 g2(D / TN, (totalRows + TM - 1) / TM, NE);
    gemm_cp<false><<<g2, NTH, SMEM_BYTES>>>(b2);

    combine_kernel<<<(T * (D / 4) + 255) / 256, 256>>>(out, T);
}

// round 17
// speedup vs baseline: 1.3441x; 1.0221x over previous
#include <cuda_runtime.h>
#include <cuda_fp16.h>
#include <math.h>
#include <stdint.h>

#define D     1024
#define HD    4096
#define NE    8
#define TOPK  2
#define MAXT  8192
#define MAXROWS (MAXT * TOPK)
#define LN_EPS 1e-5f

// GEMM tiling
#define TM 128
#define TN 128
#define KC 64                        // 64 fp16 = 128B = swizzle atom row
#define TB 16384                     // one 128x64 fp16 tile
#define BUFB (2 * TB)                // A, B per stage (32 KB)
#define NSTAGE 3
#define SMEM_BYTES (NSTAGE * BUFB)   // 98304 -> 2 CTAs/SM
#define NTH 256                      // 8 warps, 2x4 grid of 64x32 warp tiles

// ---------------- scratch ----------------------------------------------------
__device__ __half g_xn [(size_t)MAXT * D];
__device__ __half g_h1 [(size_t)MAXROWS * HD];
__device__ __half g_w1 [(size_t)NE * HD * D];   // [E][H][D] transposed fp16
__device__ __half g_w2 [(size_t)NE * D * HD];   // [E][D][H] transposed fp16
__device__ float g_b1f[(size_t)NE * HD];
__device__ float g_y [(size_t)MAXROWS * D];
__device__ float g_wts[MAXROWS];
__device__ int   g_sel[MAXROWS];
__device__ int   g_rowmap[MAXROWS];
__device__ int   g_counts[NE];
__device__ int   g_offsets[NE + 1];
__device__ int   g_cursor[NE];

// ---------------- helpers ----------------------------------------------------
__device__ __forceinline__ uint32_t smem_u32(const void* p) {
    uint32_t a;
    asm("{ .reg .u64 t; cvta.to.shared.u64 t, %1; cvt.u32.u64 %0, t; }"
        : "=r"(a) : "l"(p));
    return a;
}
// swizzle: row stride 128B, XOR (row&7)*16 into column bits
#define SWZC(row, col) ((uint32_t)((row) * 128 + ((col) ^ (((row) & 7) * 16))))

#define CPASYNC16(dst, src) \
    asm volatile("cp.async.cg.shared.global [%0], [%1], 16;" \
                 :: "r"(dst), "l"(src))
#define CP_COMMIT() asm volatile("cp.async.commit_group;")
#define CP_WAIT1()  asm volatile("cp.async.wait_group 1;")
#define CP_WAIT0()  asm volatile("cp.async.wait_group 0;")

#define LDM4(r0, r1, r2, r3, addr) \
    asm volatile("ldmatrix.sync.aligned.m8n8.x4.shared.b16 {%0,%1,%2,%3}, [%4];" \
        : "=r"(r0), "=r"(r1), "=r"(r2), "=r"(r3) : "r"(addr))

#define MMA16816(c, a, b) \
    asm volatile("mma.sync.aligned.m16n8k16.row.col.f32.f16.f16.f32 " \
        "{%0,%1,%2,%3}, {%4,%5,%6,%7}, {%8,%9}, {%0,%1,%2,%3};" \
        : "+f"((c)[0]), "+f"((c)[1]), "+f"((c)[2]), "+f"((c)[3]) \
        : "r"((a)[0]), "r"((a)[1]), "r"((a)[2]), "r"((a)[3]), \
          "r"((b)[0]), "r"((b)[1]))

__device__ __forceinline__ uint32_t pack_h2(float a, float b) {
    __half2 h = __floats2half2_rn(a, b);
    return *reinterpret_cast<uint32_t*>(&h);
}

// ---------------- weight transpose + fp16 convert (+ optional scale fold) ----
__global__ __launch_bounds__(1024) void convw_kernel(
    const float* __restrict__ W, const float* __restrict__ scale,
    __half* __restrict__ oh, int KD, int NH)
{
    __shared__ float tile[32][33];
    const int e = blockIdx.z;
    const int dr = blockIdx.x * 32 + threadIdx.y;
    const int hr = blockIdx.y * 32 + threadIdx.x;
    tile[threadIdx.y][threadIdx.x] = W[((size_t)e * KD + dr) * NH + hr];
    __syncthreads();
    const int hw = blockIdx.y * 32 + threadIdx.y;
    const int dw = blockIdx.x * 32 + threadIdx.x;
    float v = tile[threadIdx.x][threadIdx.y];
    if (scale) v *= scale[(size_t)e * KD + dw];
    oh[((size_t)e * NH + hw) * KD + dw] = __float2half_rn(v);
}

// b1'[e][h] = b1[e][h] + sum_d ln_bias[e][d] * W1[e][d][h]
__global__ __launch_bounds__(256) void foldb1_kernel(
    const float* __restrict__ w1, const float* __restrict__ b1,
    const float* __restrict__ lnb)
{
    const int e = blockIdx.y;
    const int h = blockIdx.x * 256 + threadIdx.x;
    float acc = 0.f;
    const float* wp = w1 + (size_t)e * D * HD + h;
    const float* bp = lnb + (size_t)e * D;
    for (int d = 0; d < D; d++) acc = fmaf(bp[d], wp[(size_t)d * HD], acc);
    g_b1f[(size_t)e * HD + h] = b1[(size_t)e * HD + h] + acc;
}

// ---------------- routing ----------------------------------------------------
__global__ void init_kernel() {
    if (threadIdx.x < NE) g_counts[threadIdx.x] = 0;
}

__global__ __launch_bounds__(256) void gate_ln_kernel(
    const float* __restrict__ x, const float* __restrict__ gw)
{
    const int t   = blockIdx.x;
    const int tid = threadIdx.x;
    __shared__ float sh_ws[8], sh_wq[8], sh_wl[8][8];
    __shared__ float sh_mu, sh_rstd;

    const float4 xv = reinterpret_cast<const float4*>(x + (size_t)t * D)[tid];
    float s = xv.x + xv.y + xv.z + xv.w;
    float q = xv.x * xv.x + xv.y * xv.y + xv.z * xv.z + xv.w * xv.w;

    float acc[8];
#pragma unroll
    for (int e = 0; e < 8; e++) acc[e] = 0.f;
    const float xs[4] = {xv.x, xv.y, xv.z, xv.w};
#pragma unroll
    for (int j = 0; j < 4; j++) {
        const int d = tid * 4 + j;
        const float4 g0 = *reinterpret_cast<const float4*>(gw + (size_t)d * 8);
        const float4 g1 = *reinterpret_cast<const float4*>(gw + (size_t)d * 8 + 4);
        const float xj = xs[j];
        acc[0] = fmaf(xj, g0.x, acc[0]); acc[1] = fmaf(xj, g0.y, acc[1]);
        acc[2] = fmaf(xj, g0.z, acc[2]); acc[3] = fmaf(xj, g0.w, acc[3]);
        acc[4] = fmaf(xj, g1.x, acc[4]); acc[5] = fmaf(xj, g1.y, acc[5]);
        acc[6] = fmaf(xj, g1.z, acc[6]); acc[7] = fmaf(xj, g1.w, acc[7]);
    }
#pragma unroll
    for (int o = 16; o > 0; o >>= 1) {
        s += __shfl_xor_sync(0xffffffffu, s, o);
        q += __shfl_xor_sync(0xffffffffu, q, o);
#pragma unroll
        for (int e = 0; e < 8; e++)
            acc[e] += __shfl_xor_sync(0xffffffffu, acc[e], o);
    }
    const int wid = tid >> 5, lane = tid & 31;
    if (lane == 0) {
        sh_ws[wid] = s; sh_wq[wid] = q;
#pragma unroll
        for (int e = 0; e < 8; e++) sh_wl[wid][e] = acc[e];
    }
    __syncthreads();

    if (tid == 0) {
        float S = 0.f, Q = 0.f, L[8];
#pragma unroll
        for (int e = 0; e < 8; e++) L[e] = 0.f;
        for (int w = 0; w < 8; w++) {
            S += sh_ws[w]; Q += sh_wq[w];
#pragma unroll
            for (int e = 0; e < 8; e++) L[e] += sh_wl[w][e];
        }
        const float mu = S * (1.f / (float)D);
        float var = Q * (1.f / (float)D) - mu * mu;
        if (var < 0.f) var = 0.f;
        sh_mu = mu; sh_rstd = rsqrtf(var + LN_EPS);

        float mx = L[0];
#pragma unroll
        for (int e = 1; e < 8; e++) mx = fmaxf(mx, L[e]);
        float p[8], se = 0.f;
#pragma unroll
        for (int e = 0; e < 8; e++) { p[e] = expf(L[e] - mx); se += p[e]; }
        const float inv = 1.f / se;
#pragma unroll
        for (int e = 0; e < 8; e++) p[e] *= inv;

        int i0 = 0; float p0 = p[0];
#pragma unroll
        for (int e = 1; e < 8; e++) if (p[e] > p0) { p0 = p[e]; i0 = e; }
        int i1 = -1; float p1 = -1e30f;
#pragma unroll
        for (int e = 0; e < 8; e++)
            if (e != i0 && p[e] > p1) { p1 = p[e]; i1 = e; }

        const float ew = expf(p1 - p0);
        g_sel[2 * t] = i0;  g_sel[2 * t + 1] = i1;
        g_wts[2 * t] = 1.f / (1.f + ew);
        g_wts[2 * t + 1] = ew / (1.f + ew);
        atomicAdd(&g_counts[i0], 1);
        atomicAdd(&g_counts[i1], 1);
    }
    __syncthreads();

    const float mu = sh_mu, rstd = sh_rstd;
    uint32_t* o = reinterpret_cast<uint32_t*>(g_xn + (size_t)t * D);
    o[tid * 2]     = pack_h2((xv.x - mu) * rstd, (xv.y - mu) * rstd);
    o[tid * 2 + 1] = pack_h2((xv.z - mu) * rstd, (xv.w - mu) * rstd);
}

__global__ void offsets_kernel() {
    if (threadIdx.x == 0) {
        int o = 0;
        for (int e = 0; e < NE; e++) {
            g_offsets[e] = o; g_cursor[e] = o; o += g_counts[e];
        }
        g_offsets[NE] = o;
    }
}

__global__ void scatter_kernel(int total) {
    const int i = blockIdx.x * blockDim.x + threadIdx.x;
    if (i < total) {
        const int e = g_sel[i];
        const int pos = atomicAdd(&g_cursor[e], 1);
        g_rowmap[pos] = i;
    }
}

// ---------------- cp.async pipelined mma.sync grouped GEMM -------------------
// 8 warps, 2x4 grid of 64x32 warp tiles; 2 CTAs/SM; single barrier per chunk.
template<bool G1>
__global__ __launch_bounds__(NTH, 2) void gemm_cp(
    const float* __restrict__ bias)
{
    constexpr int KTOT = G1 ? D : HD;
    constexpr int NTOT = G1 ? HD : D;
    constexpr int NC   = KTOT / KC;

    const int e    = blockIdx.z;
    const int seg0 = g_offsets[e];
    const int nseg = g_offsets[e + 1] - seg0;
    const int m0   = blockIdx.y * TM;
    if (m0 >= nseg) return;
    const int n0   = blockIdx.x * TN;

    extern __shared__ __align__(1024) char smem[];
    const uint32_t sb = smem_u32(smem);
    const int tid = threadIdx.x;

    // ---- copy mapping: row = tid>>1 (0..127), half = tid&1 (64B each) ----
    const int crow = tid >> 1;
    const int ch   = tid & 1;
    const bool cval = (m0 + crow) < nseg;
    int arow;
    if (G1) arow = cval ? (g_rowmap[seg0 + m0 + crow] >> 1) : 0;
    else    arow = cval ? (seg0 + m0 + crow) : 0;
    const __half* srcA =
        (G1 ? g_xn + (size_t)arow * D : g_h1 + (size_t)arow * HD) + ch * 32;
    const __half* srcB =
        (G1 ? g_w1 : g_w2) + ((size_t)e * NTOT + n0 + crow) * KTOT + ch * 32;

    uint32_t dsw[4];
#pragma unroll
    for (int j = 0; j < 4; j++) dsw[j] = SWZC(crow, ch * 64 + j * 16);

    auto issue = [&](int stage, int c) {
        const uint32_t base = sb + stage * BUFB;
        const int kb = c * KC;
#pragma unroll
        for (int j = 0; j < 4; j++)
            CPASYNC16(base + dsw[j], srcA + kb + j * 8);
#pragma unroll
        for (int j = 0; j < 4; j++)
            CPASYNC16(base + TB + dsw[j], srcB + kb + j * 8);
        CP_COMMIT();
    };

    // ---- consumer: 8 warps, warp_m in {0,1} (64 rows), warp_n in 0..3 (32 cols)
    const int wid    = tid >> 5;
    const int lane   = tid & 31;
    const int warp_n = wid & 3;
    const int warp_m = wid >> 2;

    float acc[4][4][4];
#pragma unroll
    for (int i = 0; i < 4; i++)
#pragma unroll
        for (int j = 0; j < 4; j++)
#pragma unroll
            for (int k = 0; k < 4; k++) acc[i][j][k] = 0.f;

    const uint32_t sel   = (uint32_t)((lane & 7) << 4);
    const uint32_t rAoff = (uint32_t)((warp_m * 64 + ((lane >> 3) & 1) * 8 + (lane & 7)) * 128);
    const uint32_t cA16  = (uint32_t)((lane >> 4) * 16);
    const uint32_t rBoff = (uint32_t)((warp_n * 32 + (lane >> 4) * 8 + (lane & 7)) * 128);
    const uint32_t cB16  = (uint32_t)(((lane >> 3) & 1) * 16);

    auto compute = [&](int stage) {
        const uint32_t aB = sb + stage * BUFB;
        const uint32_t bB = aB + TB;
#pragma unroll
        for (int ks = 0; ks < 4; ks++) {
            const uint32_t colA = ((uint32_t)(ks * 32) + cA16) ^ sel;
            const uint32_t colB = ((uint32_t)(ks * 32) + cB16) ^ sel;
            uint32_t ah[4][4], bh[4][2];
#pragma unroll
            for (int i = 0; i < 4; i++)
                LDM4(ah[i][0], ah[i][1], ah[i][2], ah[i][3],
                     aB + rAoff + (uint32_t)(i * 16 * 128) + colA);
#pragma unroll
            for (int j2 = 0; j2 < 2; j2++) {
                uint32_t t0, t1, t2, t3;
                LDM4(t0, t1, t2, t3, bB + rBoff + (uint32_t)(j2 * 16 * 128) + colB);
                bh[2*j2][0]=t0; bh[2*j2][1]=t1; bh[2*j2+1][0]=t2; bh[2*j2+1][1]=t3;
            }
#pragma unroll
            for (int i = 0; i < 4; i++)
#pragma unroll
                for (int j = 0; j < 4; j++) MMA16816(acc[i][j], ah[i], bh[j]);
        }
    };

    // ---- pipeline: 3 stages, 2 in flight, ONE barrier per chunk ----
    issue(0, 0);
    issue(1, 1);
    int stage = 0;
    for (int c = 0; c < NC; c++) {
        if (c + 1 < NC) { CP_WAIT1(); } else { CP_WAIT0(); }
        __syncthreads();          // chunk c ready; compute(c-1) done for all
        if (c + 2 < NC) {
            int s = stage + 2; if (s >= NSTAGE) s -= NSTAGE;
            issue(s, c + 2);
        }
        compute(stage);
        if (++stage == NSTAGE) stage = 0;
    }
    __syncthreads();

    // ---- epilogue ----
    {
        const int r4 = lane >> 2;
        const int c2 = 2 * (lane & 3);
        const int nb = n0 + warp_n * 32;
        const float* bp = G1 ? (g_b1f + (size_t)e * NTOT) : (bias + (size_t)e * NTOT);
        float2 bb[4];
#pragma unroll
        for (int j = 0; j < 4; j++)
            bb[j] = *reinterpret_cast<const float2*>(bp + nb + j * 8 + c2);
#pragma unroll
        for (int i = 0; i < 4; i++) {
#pragma unroll
            for (int h = 0; h < 2; h++) {
                const int mloc = warp_m * 64 + i * 16 + h * 8 + r4;
                if (m0 + mloc >= nseg) continue;
                if (G1) {
                    const size_t rb = (size_t)(seg0 + m0 + mloc) * HD + nb;
#pragma unroll
                    for (int j = 0; j < 4; j++) {
                        float y0 = acc[i][j][2*h]   + bb[j].x;
                        float y1 = acc[i][j][2*h+1] + bb[j].y;
                        y0 = 0.5f * y0 * (1.f + erff(y0 * 0.70710678118654752f));
                        y1 = 0.5f * y1 * (1.f + erff(y1 * 0.70710678118654752f));
                        reinterpret_cast<uint32_t*>(g_h1)[(rb + j * 8 + c2) >> 1] =
                            pack_h2(y0, y1);
                    }
                } else {
                    const int slot = g_rowmap[seg0 + m0 + mloc];
                    const float wt = g_wts[slot];
                    float* op = g_y + (size_t)slot * D + nb;
#pragma unroll
                    for (int j = 0; j < 4; j++) {
                        const float y0 = (acc[i][j][2*h]   + bb[j].x) * wt;
                        const float y1 = (acc[i][j][2*h+1] + bb[j].y) * wt;
                        *reinterpret_cast<float2*>(op + j * 8 + c2) = make_float2(y0, y1);
                    }
                }
            }
        }
    }
}

// ---------------- combine ----------------------------------------------------
__global__ void combine_kernel(float* __restrict__ out, int T) {
    const int nd4 = D / 4;
    const int i = blockIdx.x * blockDim.x + threadIdx.x;
    if (i >= T * nd4) return;
    const int t = i / nd4, d4 = i % nd4;
    const float4* y4 = reinterpret_cast<const float4*>(g_y);
    const float4 a = y4[(size_t)(2 * t) * nd4 + d4];
    const float4 b = y4[(size_t)(2 * t + 1) * nd4 + d4];
    reinterpret_cast<float4*>(out)[i] =
        make_float4(a.x + b.x, a.y + b.y, a.z + b.z, a.w + b.w);
}

// ---------------- launch -----------------------------------------------------
extern "C" void kernel_launch(void* const* d_in, const int* in_sizes, int n_in,
                              void* d_out, int out_size)
{
    const float* x   = (const float*)d_in[0];
    const float* gw  = (const float*)d_in[1];
    const float* lns = (const float*)d_in[2];
    const float* lnb = (const float*)d_in[3];
    const float* w1  = (const float*)d_in[4];
    const float* b1  = (const float*)d_in[5];
    const float* w2  = (const float*)d_in[6];
    const float* b2  = (const float*)d_in[7];
    float* out = (float*)d_out;

    const int T = in_sizes[0] / D;
    const int totalRows = T * TOPK;

    cudaFuncSetAttribute(gemm_cp<true>,
                         cudaFuncAttributeMaxDynamicSharedMemorySize, SMEM_BYTES);
    cudaFuncSetAttribute(gemm_cp<false>,
                         cudaFuncAttributeMaxDynamicSharedMemorySize, SMEM_BYTES);

    __half *w1p, *w2p;
    cudaGetSymbolAddress((void**)&w1p, g_w1);
    cudaGetSymbolAddress((void**)&w2p, g_w2);

    dim3 blk32(32, 32);
    convw_kernel<<<dim3(D / 32, HD / 32, NE), blk32>>>(w1, lns, w1p, D, HD);
    convw_kernel<<<dim3(HD / 32, D / 32, NE), blk32>>>(w2, nullptr, w2p, HD, D);
    foldb1_kernel<<<dim3(HD / 256, NE), 256>>>(w1, b1, lnb);

    init_kernel<<<1, 32>>>();
    gate_ln_kernel<<<T, 256>>>(x, gw);
    offsets_kernel<<<1, 32>>>();
    scatter_kernel<<<(totalRows + 255) / 256, 256>>>(totalRows);

    dim3 g1(HD / TN, (totalRows + TM - 1) / TM, NE);
    gemm_cp<true><<<g1, NTH, SMEM_BYTES>>>(nullptr);

    dim3 g2(D / TN, (totalRows + TM - 1) / TM, NE);
    gemm_cp<false><<<g2, NTH, SMEM_BYTES>>>(b2);

    combine_kernel<<<(T * (D / 4) + 255) / 256, 256>>>(out, T);
}